// round 16
// baseline (speedup 1.0000x reference)
#include <cuda_runtime.h>
#include <cuda_bf16.h>
#include <math.h>
#include <stdint.h>

// ---------------- problem constants ----------------
#define BB     2
#define S_IMG  2048
#define S_TXT  256
#define S_TOT  2304
#define NH     24
#define DHD    128
#define DD     3072
#define ATT_SCALE 0.08838834764831845f
#define RMS_EPS   1e-5f

#define M_IMG  (BB * S_IMG)          // 4096
#define M_TXT  (BB * S_TXT)          // 512
#define M_O    (BB * S_TOT)          // 4608
#define IMG_OUT_ELEMS (M_IMG * DD)

// ---------------- device scratch ----------------
__device__ __nv_bfloat16 g_Qh[BB * NH * S_TOT * DHD], g_Ql[BB * NH * S_TOT * DHD];
__device__ __nv_bfloat16 g_Kh[BB * NH * S_TOT * DHD], g_Kl[BB * NH * S_TOT * DHD];
__device__ __nv_bfloat16 g_Vh[BB * NH * S_TOT * DHD], g_Vl[BB * NH * S_TOT * DHD];

__device__ __nv_bfloat16 g_Whi[8][DD * DD];   // transposed [N,K] bf16 hi
__device__ __nv_bfloat16 g_Wlo[8][DD * DD];   // transposed [N,K] bf16 lo
__device__ __nv_bfloat16 g_Hhi[M_IMG * DD], g_Hlo[M_IMG * DD];
__device__ __nv_bfloat16 g_Ehi[M_TXT * DD], g_Elo[M_TXT * DD];
__device__ __nv_bfloat16 g_Shi[M_O * DD],  g_Slo[M_O * DD];   // attn-out split [B,S,D]

// ---------------- PTX helpers ----------------
__device__ __forceinline__ uint32_t smem_u32(const void* p) {
    uint32_t a;
    asm("{ .reg .u64 t; cvta.to.shared.u64 t, %1; cvt.u32.u64 %0, t; }" : "=r"(a) : "l"(p));
    return a;
}
#define CP_ASYNC16(sa, gp) \
    asm volatile("cp.async.cg.shared.global [%0], [%1], 16;" :: "r"(sa), "l"(gp) : "memory")
#define CP_COMMIT() asm volatile("cp.async.commit_group;" ::: "memory")
#define CP_WAIT(n)  asm volatile("cp.async.wait_group %0;" :: "n"(n) : "memory")

__device__ __forceinline__ void ldsm_x4(uint32_t& r0, uint32_t& r1, uint32_t& r2,
                                        uint32_t& r3, uint32_t addr) {
    asm volatile("ldmatrix.sync.aligned.m8n8.x4.shared.b16 {%0,%1,%2,%3}, [%4];"
                 : "=r"(r0), "=r"(r1), "=r"(r2), "=r"(r3) : "r"(addr));
}
__device__ __forceinline__ void ldsm_x4_t(uint32_t& r0, uint32_t& r1, uint32_t& r2,
                                          uint32_t& r3, uint32_t addr) {
    asm volatile("ldmatrix.sync.aligned.m8n8.x4.trans.shared.b16 {%0,%1,%2,%3}, [%4];"
                 : "=r"(r0), "=r"(r1), "=r"(r2), "=r"(r3) : "r"(addr));
}
__device__ __forceinline__ void mma16816(float* c, const uint32_t* a, const uint32_t* b) {
    asm volatile(
        "mma.sync.aligned.m16n8k16.row.col.f32.bf16.bf16.f32 "
        "{%0,%1,%2,%3}, {%4,%5,%6,%7}, {%8,%9}, {%0,%1,%2,%3};"
        : "+f"(c[0]), "+f"(c[1]), "+f"(c[2]), "+f"(c[3])
        : "r"(a[0]), "r"(a[1]), "r"(a[2]), "r"(a[3]), "r"(b[0]), "r"(b[1]));
}
__device__ __forceinline__ uint32_t pack_bf2(float a, float b) {
    uint32_t r;
    asm("cvt.rn.bf16x2.f32 %0, %1, %2;" : "=r"(r) : "f"(b), "f"(a));
    return r;
}

// ---------------- gemm smem geometry (2-stage, 2 CTAs/SM) ----------------
#define KC     32
#define NIT    (DD / KC)          // 96
#define ROWB   80
#define TILEB  (128 * ROWB)       // 10240
#define STAGEB (4 * TILEB)        // 40960
#define GEMM_SMEM (2 * STAGEB)    // 81920

// ---------------- kernel arg structs ----------------
struct QKVArgs {
    const __nv_bfloat16 *Hhi, *Hlo, *Ehi, *Elo;
    const __nv_bfloat16 *Wh[6], *Wl[6];
    const float *bias[6];
    const float *gq, *gk, *gqa, *gka;
    const float *cosI, *sinI, *cosT, *sinT;
    __nv_bfloat16 *Qh, *Ql, *Kh, *Kl, *Vh, *Vl;
};
struct WOArgs {
    const __nv_bfloat16 *Shi, *Slo;
    const __nv_bfloat16 *WhImg, *WlImg, *WhTxt, *WlTxt;
    const float *bImg, *bTxt;
    float *outImg, *outTxt;
};
struct WSplitArgs {
    const float* W[8];
    __nv_bfloat16 *Whi, *Wlo;
};

// =============================================================================
// Unified QKV projection (known-good 2 CTAs/SM)
// =============================================================================
__global__ void __launch_bounds__(256, 2) qkv_mma(QKVArgs P)
{
    extern __shared__ char smraw[];
    const uint32_t sb = smem_u32(smraw);
    const int t = threadIdx.x, lane = t & 31, wid = t >> 5;
    const int warp_m = wid & 1, warp_n = wid >> 1;
    const int z = blockIdx.z;
    const bool img = (blockIdx.y < 32);
    const int bm = (img ? blockIdx.y : (blockIdx.y - 32)) << 7;
    const int bn = blockIdx.x << 7;
    const int wi = img ? z : (z + 3);

    const __nv_bfloat16* Ahi = img ? P.Hhi : P.Ehi;
    const __nv_bfloat16* Alo = img ? P.Hlo : P.Elo;
    const __nv_bfloat16* Bhi = P.Wh[wi];
    const __nv_bfloat16* Blo = P.Wl[wi];
    const float* bias = P.bias[wi];

    const __nv_bfloat16* gsrc[8];
    uint32_t sdst[8];
#pragma unroll
    for (int i = 0; i < 8; i++) {
        int buf = i >> 1;
        int c = t + 256 * (i & 1);
        int row = c >> 2, kc = c & 3;
        const __nv_bfloat16* base = (buf == 0) ? Ahi : (buf == 1) ? Alo
                                  : (buf == 2) ? Bhi : Blo;
        long grow = (buf < 2) ? (long)(bm + row) : (long)(bn + row);
        gsrc[i] = base + (size_t)grow * DD + kc * 8;
        sdst[i] = sb + buf * TILEB + row * ROWB + kc * 16;
    }

    const uint32_t aBase = sb + (warp_m * 64 + (lane & 15)) * ROWB + (lane >> 4) * 16;
    const int brow = (lane & 7) + (((lane >> 4) & 1) << 3);
    const int bkh  = (lane >> 3) & 1;
    const uint32_t bBase = sb + 2 * TILEB + (warp_n * 32 + brow) * ROWB + bkh * 16;

    float acc[4][4][4];
#pragma unroll
    for (int mf = 0; mf < 4; mf++)
#pragma unroll
        for (int nf = 0; nf < 4; nf++)
#pragma unroll
            for (int r = 0; r < 4; r++) acc[mf][nf][r] = 0.f;

    {
#pragma unroll
        for (int i = 0; i < 8; i++) CP_ASYNC16(sdst[i], gsrc[i]);
        CP_COMMIT();
    }

    for (int it = 0; it < NIT; it++) {
        const int s = it & 1;
        if (it + 1 < NIT) {
            const int k0 = (it + 1) * KC;
            const uint32_t so = (s ^ 1) * STAGEB;
#pragma unroll
            for (int i = 0; i < 8; i++) CP_ASYNC16(sdst[i] + so, gsrc[i] + k0);
            CP_COMMIT();
            CP_WAIT(1);
        } else {
            CP_WAIT(0);
        }
        __syncthreads();

        const uint32_t sbase = s * STAGEB;
#pragma unroll
        for (int ks = 0; ks < 2; ks++) {
            uint32_t ah[4][4], al[4][4];
#pragma unroll
            for (int mf = 0; mf < 4; mf++) {
                uint32_t ad = aBase + sbase + mf * (16 * ROWB) + ks * 32;
                ldsm_x4(ah[mf][0], ah[mf][1], ah[mf][2], ah[mf][3], ad);
                ldsm_x4(al[mf][0], al[mf][1], al[mf][2], al[mf][3], ad + TILEB);
            }
            uint32_t bh[4][2], bl2[4][2];
#pragma unroll
            for (int nf2 = 0; nf2 < 2; nf2++) {
                uint32_t bd = bBase + sbase + nf2 * (16 * ROWB) + ks * 32;
                ldsm_x4(bh[2*nf2][0], bh[2*nf2][1], bh[2*nf2+1][0], bh[2*nf2+1][1], bd);
                ldsm_x4(bl2[2*nf2][0], bl2[2*nf2][1], bl2[2*nf2+1][0], bl2[2*nf2+1][1], bd + TILEB);
            }
#pragma unroll
            for (int mf = 0; mf < 4; mf++)
#pragma unroll
                for (int nf = 0; nf < 4; nf++) {
                    mma16816(acc[mf][nf], ah[mf], bh[nf]);
                    mma16816(acc[mf][nf], ah[mf], bl2[nf]);
                    mma16816(acc[mf][nf], al[mf], bh[nf]);
                }
        }
        __syncthreads();
    }

    // ---------------- epilogue ----------------
    const int rgrp = lane >> 2, qlane = lane & 3;
    const int h = blockIdx.x;
    const int seg = img ? S_IMG : S_TXT;
    const int sofs = img ? 0 : S_IMG;
    __nv_bfloat16* Xh = (z == 0) ? P.Qh : (z == 1) ? P.Kh : P.Vh;
    __nv_bfloat16* Xl = (z == 0) ? P.Ql : (z == 1) ? P.Kl : P.Vl;

#pragma unroll
    for (int mf = 0; mf < 4; mf++)
#pragma unroll
        for (int nf = 0; nf < 4; nf++) {
            int colg = bn + warp_n * 32 + nf * 8 + qlane * 2;
            float2 bv = *(const float2*)(bias + colg);
            acc[mf][nf][0] += bv.x; acc[mf][nf][1] += bv.y;
            acc[mf][nf][2] += bv.x; acc[mf][nf][3] += bv.y;
        }

    float rns[4][2];
    if (z < 2) {
        float* ssum = (float*)smraw;
#pragma unroll
        for (int mf = 0; mf < 4; mf++)
#pragma unroll
            for (int half = 0; half < 2; half++) {
                float ss = 0.f;
#pragma unroll
                for (int nf = 0; nf < 4; nf++) {
                    float x0 = acc[mf][nf][half * 2 + 0];
                    float x1 = acc[mf][nf][half * 2 + 1];
                    ss += x0 * x0 + x1 * x1;
                }
                ss += __shfl_xor_sync(0xffffffffu, ss, 1);
                ss += __shfl_xor_sync(0xffffffffu, ss, 2);
                if (qlane == 0)
                    ssum[(warp_m * 64 + mf * 16 + half * 8 + rgrp) * 4 + warp_n] = ss;
            }
        __syncthreads();
#pragma unroll
        for (int mf = 0; mf < 4; mf++)
#pragma unroll
            for (int half = 0; half < 2; half++) {
                int lrow = warp_m * 64 + mf * 16 + half * 8 + rgrp;
                float tot = ssum[lrow * 4 + 0] + ssum[lrow * 4 + 1] +
                            ssum[lrow * 4 + 2] + ssum[lrow * 4 + 3];
                rns[mf][half] = rsqrtf(tot * (1.f / DHD) + RMS_EPS);
            }
    }

    const float* g = (z == 0) ? (img ? P.gq : P.gqa)
                   : (z == 1) ? (img ? P.gk : P.gka) : (const float*)0;
    const float* cosT2 = img ? P.cosI : P.cosT;
    const float* sinT2 = img ? P.sinI : P.sinT;

#pragma unroll
    for (int mf = 0; mf < 4; mf++)
#pragma unroll
        for (int half = 0; half < 2; half++) {
            int lrow = warp_m * 64 + mf * 16 + half * 8 + rgrp;
            int m = bm + lrow;
            int b = m / seg, sl = m % seg;
            int sq = sofs + sl;
            size_t obase = (((size_t)(b * NH + h)) * S_TOT + sq) * DHD;
#pragma unroll
            for (int nf = 0; nf < 4; nf++) {
                int colh = warp_n * 32 + nf * 8 + qlane * 2;
                float x0 = acc[mf][nf][half * 2 + 0];
                float x1 = acc[mf][nf][half * 2 + 1];
                if (z < 2) {
                    float rn = rns[mf][half];
                    x0 *= rn * g[colh];
                    x1 *= rn * g[colh + 1];
                    int fi = colh >> 1;
                    float c = cosT2[sl * (DHD / 2) + fi];
                    float sv = sinT2[sl * (DHD / 2) + fi];
                    float o0 = x0 * c - x1 * sv;
                    float o1 = x0 * sv + x1 * c;
                    x0 = o0; x1 = o1;
                }
                uint32_t hp = pack_bf2(x0, x1);
                *(uint32_t*)((char*)Xh + (obase + colh) * 2) = hp;
                float ha = __uint_as_float((hp & 0xffffu) << 16);
                float hb = __uint_as_float(hp & 0xffff0000u);
                *(uint32_t*)((char*)Xl + (obase + colh) * 2) = pack_bf2(x0 - ha, x1 - hb);
            }
        }
}

// =============================================================================
// Unified output projection (known-good)
// =============================================================================
__global__ void __launch_bounds__(256, 2) wo_mma(WOArgs P)
{
    extern __shared__ char smraw[];
    const uint32_t sb = smem_u32(smraw);
    const int t = threadIdx.x, lane = t & 31, wid = t >> 5;
    const int warp_m = wid & 1, warp_n = wid >> 1;
    const bool img = (blockIdx.y < 32);
    const int bm = (img ? blockIdx.y : (blockIdx.y - 32)) << 7;
    const int bn = blockIdx.x << 7;

    const __nv_bfloat16* Bhi = img ? P.WhImg : P.WhTxt;
    const __nv_bfloat16* Blo = img ? P.WlImg : P.WlTxt;
    const float* bias = img ? P.bImg : P.bTxt;
    float* out = img ? P.outImg : P.outTxt;
    const int seg = img ? S_IMG : S_TXT;
    const int sofs = img ? 0 : S_IMG;

    const __nv_bfloat16* gsrc[8];
    uint32_t sdst[8];
#pragma unroll
    for (int i = 0; i < 8; i++) {
        int buf = i >> 1;
        int c = t + 256 * (i & 1);
        int row = c >> 2, kc = c & 3;
        const __nv_bfloat16* base = (buf == 0) ? P.Shi : (buf == 1) ? P.Slo
                                  : (buf == 2) ? Bhi : Blo;
        long grow;
        if (buf < 2) {
            int m = bm + row;
            grow = (long)(m / seg) * S_TOT + sofs + (m % seg);
        } else {
            grow = bn + row;
        }
        gsrc[i] = base + (size_t)grow * DD + kc * 8;
        sdst[i] = sb + buf * TILEB + row * ROWB + kc * 16;
    }

    const uint32_t aBase = sb + (warp_m * 64 + (lane & 15)) * ROWB + (lane >> 4) * 16;
    const int brow = (lane & 7) + (((lane >> 4) & 1) << 3);
    const int bkh  = (lane >> 3) & 1;
    const uint32_t bBase = sb + 2 * TILEB + (warp_n * 32 + brow) * ROWB + bkh * 16;

    float acc[4][4][4];
#pragma unroll
    for (int mf = 0; mf < 4; mf++)
#pragma unroll
        for (int nf = 0; nf < 4; nf++)
#pragma unroll
            for (int r = 0; r < 4; r++) acc[mf][nf][r] = 0.f;

    {
#pragma unroll
        for (int i = 0; i < 8; i++) CP_ASYNC16(sdst[i], gsrc[i]);
        CP_COMMIT();
    }

    for (int it = 0; it < NIT; it++) {
        const int s = it & 1;
        if (it + 1 < NIT) {
            const int k0 = (it + 1) * KC;
            const uint32_t so = (s ^ 1) * STAGEB;
#pragma unroll
            for (int i = 0; i < 8; i++) CP_ASYNC16(sdst[i] + so, gsrc[i] + k0);
            CP_COMMIT();
            CP_WAIT(1);
        } else {
            CP_WAIT(0);
        }
        __syncthreads();

        const uint32_t sbase = s * STAGEB;
#pragma unroll
        for (int ks = 0; ks < 2; ks++) {
            uint32_t ah[4][4], al[4][4];
#pragma unroll
            for (int mf = 0; mf < 4; mf++) {
                uint32_t ad = aBase + sbase + mf * (16 * ROWB) + ks * 32;
                ldsm_x4(ah[mf][0], ah[mf][1], ah[mf][2], ah[mf][3], ad);
                ldsm_x4(al[mf][0], al[mf][1], al[mf][2], al[mf][3], ad + TILEB);
            }
            uint32_t bh[4][2], bl2[4][2];
#pragma unroll
            for (int nf2 = 0; nf2 < 2; nf2++) {
                uint32_t bd = bBase + sbase + nf2 * (16 * ROWB) + ks * 32;
                ldsm_x4(bh[2*nf2][0], bh[2*nf2][1], bh[2*nf2+1][0], bh[2*nf2+1][1], bd);
                ldsm_x4(bl2[2*nf2][0], bl2[2*nf2][1], bl2[2*nf2+1][0], bl2[2*nf2+1][1], bd + TILEB);
            }
#pragma unroll
            for (int mf = 0; mf < 4; mf++)
#pragma unroll
                for (int nf = 0; nf < 4; nf++) {
                    mma16816(acc[mf][nf], ah[mf], bh[nf]);
                    mma16816(acc[mf][nf], ah[mf], bl2[nf]);
                    mma16816(acc[mf][nf], al[mf], bh[nf]);
                }
        }
        __syncthreads();
    }

#pragma unroll
    for (int mf = 0; mf < 4; mf++) {
        const int rbase = bm + warp_m * 64 + mf * 16 + (lane >> 2);
#pragma unroll
        for (int half = 0; half < 2; half++) {
            const int mrow = rbase + half * 8;
            float* orow = out + (size_t)mrow * DD;
#pragma unroll
            for (int nf = 0; nf < 4; nf++) {
                const int col = bn + warp_n * 32 + nf * 8 + (lane & 3) * 2;
                float2 bv = *(const float2*)(bias + col);
                float2 v;
                v.x = acc[mf][nf][half * 2 + 0] + bv.x;
                v.y = acc[mf][nf][half * 2 + 1] + bv.y;
                *(float2*)(orow + col) = v;
            }
        }
    }
}

// =============================================================================
// merged weight transpose + bf16 split: grid (96, 96, 8)
// =============================================================================
__global__ void __launch_bounds__(256) wsplit_all(WSplitArgs P)
{
    __shared__ float ts[32][33];
    const int tx = threadIdx.x, ty = threadIdx.y;
    const int n0 = blockIdx.x << 5, k0 = blockIdx.y << 5;
    const int z = blockIdx.z;
    const float* W = P.W[z];
    __nv_bfloat16* Thi = P.Whi + (size_t)z * DD * DD;
    __nv_bfloat16* Tlo = P.Wlo + (size_t)z * DD * DD;
#pragma unroll
    for (int i = 0; i < 4; i++)
        ts[ty + 8 * i][tx] = W[(size_t)(k0 + ty + 8 * i) * DD + n0 + tx];
    __syncthreads();
#pragma unroll
    for (int i = 0; i < 4; i++) {
        float v = ts[tx][ty + 8 * i];
        __nv_bfloat16 h = __float2bfloat16(v);
        float lo = v - __bfloat162float(h);
        size_t o = (size_t)(n0 + ty + 8 * i) * DD + k0 + tx;
        Thi[o] = h;
        Tlo[o] = __float2bfloat16(lo);
    }
}

// =============================================================================
// elementwise bf16 split
// =============================================================================
__global__ void __launch_bounds__(256) asplit_kernel(
    const float* __restrict__ X, __nv_bfloat16* __restrict__ hi,
    __nv_bfloat16* __restrict__ lo, int n4)
{
    int i = blockIdx.x * 256 + threadIdx.x;
    if (i >= n4) return;
    float4 v = ((const float4*)X)[i];
    __nv_bfloat16 h0 = __float2bfloat16(v.x), h1 = __float2bfloat16(v.y);
    __nv_bfloat16 h2 = __float2bfloat16(v.z), h3 = __float2bfloat16(v.w);
    __nv_bfloat162* hp = (__nv_bfloat162*)hi;
    __nv_bfloat162* lp = (__nv_bfloat162*)lo;
    hp[2 * i + 0] = __nv_bfloat162(h0, h1);
    hp[2 * i + 1] = __nv_bfloat162(h2, h3);
    lp[2 * i + 0] = __nv_bfloat162(__float2bfloat16(v.x - __bfloat162float(h0)),
                                   __float2bfloat16(v.y - __bfloat162float(h1)));
    lp[2 * i + 1] = __nv_bfloat162(__float2bfloat16(v.z - __bfloat162float(h2)),
                                   __float2bfloat16(v.w - __bfloat162float(h3)));
}

// =============================================================================
// HMMA flash attention: BQ=64, BK=32, 4 warps (128 thr), 2 CTAs/SM.
// Q fragments cached in registers. Double-buffered cp.async KV.
// =============================================================================
#define SPB    272
#define ATSB32 (32 * SPB)          // one 32-row K/V tile = 8704 B
#define AQB64  (64 * SPB)          // one 64-row Q tile = 17408 B
#define SM_QH2  0
#define SM_QL2  AQB64
#define SM_ST02 (2 * AQB64)        // 34816
#define SM_STSZ2 (4 * ATSB32)      // 34816 per stage (Kh,Kl,Vh,Vl)
#define SM_BIAS2 (SM_ST02 + 2 * SM_STSZ2)   // 104448
#define ATT_SMEM2 (SM_BIAS2 + S_TXT * 4)    // 105472
#define NKT2 (S_TOT / 32)          // 72

__global__ void __launch_bounds__(128, 2) attn_mma(
    const __nv_bfloat16* __restrict__ Qh, const __nv_bfloat16* __restrict__ Ql,
    const __nv_bfloat16* __restrict__ Kh, const __nv_bfloat16* __restrict__ Kl,
    const __nv_bfloat16* __restrict__ Vh, const __nv_bfloat16* __restrict__ Vl,
    const int* __restrict__ mask,
    __nv_bfloat16* __restrict__ Ohi, __nv_bfloat16* __restrict__ Olo)
{
    extern __shared__ char smraw[];
    const uint32_t sb = smem_u32(smraw);
    const int t = threadIdx.x, lane = t & 31, w = t >> 5;   // w in 0..3
    const int bh = blockIdx.y, b = bh / NH, h = bh % NH;
    const int q0 = blockIdx.x * 64;
    const size_t bhoff = (size_t)bh * S_TOT * DHD;

    for (int i = t; i < S_TXT; i += 128)
        *(float*)(smraw + SM_BIAS2 + i * 4) = (mask[b * S_TXT + i] == 0) ? -1e9f : 0.f;

    const __nv_bfloat16* kvsrc[4] = { Kh + bhoff, Kl + bhoff, Vh + bhoff, Vl + bhoff };
    // KV stage: 4 tiles x 32 rows x 16 chunks = 2048 chunks, 16 per thread
    auto issue = [&](int kt, int s) {
        const uint32_t stb = sb + SM_ST02 + s * SM_STSZ2;
        const int k0 = kt * 32;
#pragma unroll
        for (int c = 0; c < 16; c++) {
            int idx = t + 128 * c;
            int buf = idx >> 9, rem = idx & 511;
            int row = rem >> 4, ch = rem & 15;
            const __nv_bfloat16* gp = kvsrc[buf] + (size_t)(k0 + row) * DHD + ch * 8;
            uint32_t sa = stb + buf * ATSB32 + row * SPB + ch * 16;
            CP_ASYNC16(sa, gp);
        }
    };

    issue(0, 0);
    CP_COMMIT();

    // Q load: 2 bufs x 64 rows x 16 chunks = 2048 chunks, 16 per thread
    {
        const __nv_bfloat16* qsrc[2] = { Qh + bhoff + (size_t)q0 * DHD,
                                         Ql + bhoff + (size_t)q0 * DHD };
#pragma unroll
        for (int i = 0; i < 16; i++) {
            int idx = t + 128 * i;
            int buf = idx >> 10, rem = idx & 1023;
            int row = rem >> 4, ch = rem & 15;
            uint4 v = *(const uint4*)(qsrc[buf] + (size_t)row * DHD + ch * 8);
            *(uint4*)(smraw + buf * AQB64 + row * SPB + ch * 16) = v;
        }
    }
    __syncthreads();

    // cache Q fragments in registers (64 regs)
    const uint32_t qA = sb + SM_QH2 + (w * 16 + (lane & 15)) * SPB + (lane >> 4) * 16;
    uint32_t qfh[8][4], qfl[8][4];
#pragma unroll
    for (int ks = 0; ks < 8; ks++) {
        ldsm_x4(qfh[ks][0], qfh[ks][1], qfh[ks][2], qfh[ks][3], qA + ks * 32);
        ldsm_x4(qfl[ks][0], qfl[ks][1], qfl[ks][2], qfl[ks][3], qA + AQB64 + ks * 32);
    }

    const uint32_t kBrel = ((lane >> 4) * 8 + (lane & 7)) * SPB + ((lane >> 3) & 1) * 16;
    const uint32_t vBrel = (lane & 15) * SPB + (lane >> 4) * 16;

    float m0 = -1e30f, m1 = -1e30f, l0 = 0.f, l1 = 0.f;
    float o[16][4];
#pragma unroll
    for (int nf = 0; nf < 16; nf++)
#pragma unroll
        for (int e = 0; e < 4; e++) o[nf][e] = 0.f;

    for (int kt = 0; kt < NKT2; kt++) {
        const int s = kt & 1;
        if (kt + 1 < NKT2) { issue(kt + 1, s ^ 1); CP_COMMIT(); CP_WAIT(1); }
        else               { CP_WAIT(0); }
        __syncthreads();

        const uint32_t stb = sb + SM_ST02 + s * SM_STSZ2;

        // ---- QK^T (3-pass) -> sc[4][4], 32 keys
        float sc[4][4];
#pragma unroll
        for (int j = 0; j < 4; j++)
#pragma unroll
            for (int e = 0; e < 4; e++) sc[j][e] = 0.f;

#pragma unroll
        for (int ks = 0; ks < 8; ks++) {
#pragma unroll
            for (int j2 = 0; j2 < 2; j2++) {
                uint32_t kb[4], klr[4];
                uint32_t kd = stb + kBrel + j2 * (16 * SPB) + ks * 32;
                ldsm_x4(kb[0], kb[1], kb[2], kb[3], kd);
                ldsm_x4(klr[0], klr[1], klr[2], klr[3], kd + ATSB32);
                mma16816(sc[2 * j2 + 0], qfh[ks], kb);
                mma16816(sc[2 * j2 + 1], qfh[ks], kb + 2);
                mma16816(sc[2 * j2 + 0], qfh[ks], klr);
                mma16816(sc[2 * j2 + 1], qfh[ks], klr + 2);
                mma16816(sc[2 * j2 + 0], qfl[ks], kb);
                mma16816(sc[2 * j2 + 1], qfl[ks], kb + 2);
            }
        }

        // ---- scale + mask bias
        const bool txt_tile = (kt * 32 + 31 >= S_IMG);
#pragma unroll
        for (int j = 0; j < 4; j++) {
            int colb = kt * 32 + j * 8 + (lane & 3) * 2;
            float b0v = 0.f, b1v = 0.f;
            if (txt_tile) {
                if (colb + 0 >= S_IMG) b0v = *(float*)(smraw + SM_BIAS2 + (colb + 0 - S_IMG) * 4);
                if (colb + 1 >= S_IMG) b1v = *(float*)(smraw + SM_BIAS2 + (colb + 1 - S_IMG) * 4);
            }
            sc[j][0] = sc[j][0] * ATT_SCALE + b0v;
            sc[j][1] = sc[j][1] * ATT_SCALE + b1v;
            sc[j][2] = sc[j][2] * ATT_SCALE + b0v;
            sc[j][3] = sc[j][3] * ATT_SCALE + b1v;
        }

        // ---- online softmax (rows lane>>2 and +8, warp-local)
        float mx0 = -1e30f, mx1 = -1e30f;
#pragma unroll
        for (int j = 0; j < 4; j++) {
            mx0 = fmaxf(mx0, fmaxf(sc[j][0], sc[j][1]));
            mx1 = fmaxf(mx1, fmaxf(sc[j][2], sc[j][3]));
        }
        mx0 = fmaxf(mx0, __shfl_xor_sync(0xffffffffu, mx0, 1));
        mx0 = fmaxf(mx0, __shfl_xor_sync(0xffffffffu, mx0, 2));
        mx1 = fmaxf(mx1, __shfl_xor_sync(0xffffffffu, mx1, 1));
        mx1 = fmaxf(mx1, __shfl_xor_sync(0xffffffffu, mx1, 2));
        float mn0 = fmaxf(m0, mx0), mn1 = fmaxf(m1, mx1);
        float al0 = __expf(m0 - mn0), al1 = __expf(m1 - mn1);
        float rs0 = 0.f, rs1 = 0.f;
#pragma unroll
        for (int j = 0; j < 4; j++) {
            sc[j][0] = __expf(sc[j][0] - mn0); rs0 += sc[j][0];
            sc[j][1] = __expf(sc[j][1] - mn0); rs0 += sc[j][1];
            sc[j][2] = __expf(sc[j][2] - mn1); rs1 += sc[j][2];
            sc[j][3] = __expf(sc[j][3] - mn1); rs1 += sc[j][3];
        }
        rs0 += __shfl_xor_sync(0xffffffffu, rs0, 1);
        rs0 += __shfl_xor_sync(0xffffffffu, rs0, 2);
        rs1 += __shfl_xor_sync(0xffffffffu, rs1, 1);
        rs1 += __shfl_xor_sync(0xffffffffu, rs1, 2);
        l0 = l0 * al0 + rs0; m0 = mn0;
        l1 = l1 * al1 + rs1; m1 = mn1;
#pragma unroll
        for (int nf = 0; nf < 16; nf++) {
            o[nf][0] *= al0; o[nf][1] *= al0;
            o[nf][2] *= al1; o[nf][3] *= al1;
        }

        // ---- P @ V (3-pass), P frags direct from sc
        const uint32_t vtb = stb + 2 * ATSB32;
#pragma unroll
        for (int ksv = 0; ksv < 2; ksv++) {
            uint32_t ah[4], alr[4];
#pragma unroll
            for (int q = 0; q < 4; q++) {
                int j = 2 * ksv + (q >> 1);
                float pa = sc[j][(q & 1) * 2 + 0];
                float pb = sc[j][(q & 1) * 2 + 1];
                uint32_t hp = pack_bf2(pa, pb);
                ah[q] = hp;
                float ha = __uint_as_float((hp & 0xffffu) << 16);
                float hb2 = __uint_as_float(hp & 0xffff0000u);
                alr[q] = pack_bf2(pa - ha, pb - hb2);
            }
#pragma unroll
            for (int ch = 0; ch < 8; ch++) {
                uint32_t vb[4], vlr[4];
                uint32_t vd = vtb + vBrel + ksv * (16 * SPB) + ch * 32;
                ldsm_x4_t(vb[0], vb[1], vb[2], vb[3], vd);
                ldsm_x4_t(vlr[0], vlr[1], vlr[2], vlr[3], vd + ATSB32);
                mma16816(o[2 * ch + 0], ah, vb);
                mma16816(o[2 * ch + 1], ah, vb + 2);
                mma16816(o[2 * ch + 0], ah, vlr);
                mma16816(o[2 * ch + 1], ah, vlr + 2);
                mma16816(o[2 * ch + 0], alr, vb);
                mma16816(o[2 * ch + 1], alr, vb + 2);
            }
        }
        __syncthreads();
    }

    // ---- epilogue: normalize, split hi/lo, write [B,S,D]
    float inv0 = 1.f / l0, inv1 = 1.f / l1;
    int r0 = q0 + w * 16 + (lane >> 2), r1 = r0 + 8;
    size_t base0 = ((size_t)(b * S_TOT + r0)) * DD + h * DHD;
    size_t base1 = ((size_t)(b * S_TOT + r1)) * DD + h * DHD;
#pragma unroll
    for (int nf = 0; nf < 16; nf++) {
        int d = nf * 8 + (lane & 3) * 2;
        float v0 = o[nf][0] * inv0, v1 = o[nf][1] * inv0;
        uint32_t hp = pack_bf2(v0, v1);
        *(uint32_t*)((char*)Ohi + (base0 + d) * 2) = hp;
        float ha = __uint_as_float((hp & 0xffffu) << 16);
        float hb2 = __uint_as_float(hp & 0xffff0000u);
        *(uint32_t*)((char*)Olo + (base0 + d) * 2) = pack_bf2(v0 - ha, v1 - hb2);

        float u0 = o[nf][2] * inv1, u1 = o[nf][3] * inv1;
        uint32_t hq = pack_bf2(u0, u1);
        *(uint32_t*)((char*)Ohi + (base1 + d) * 2) = hq;
        float hc = __uint_as_float((hq & 0xffffu) << 16);
        float hd = __uint_as_float(hq & 0xffff0000u);
        *(uint32_t*)((char*)Olo + (base1 + d) * 2) = pack_bf2(u0 - hc, u1 - hd);
    }
}

// =============================================================================
// Launch
// =============================================================================
extern "C" void kernel_launch(void* const* d_in, const int* in_sizes, int n_in,
                              void* d_out, int out_size)
{
    const float* hidden = (const float*)d_in[0];
    const float* enc    = (const float*)d_in[1];
    const int*   mask   = (const int*)d_in[2];
    const int fb = (in_sizes[3] == 2) ? 4 : 3;
    const float* cosI = (const float*)d_in[fb + 0];
    const float* sinI = (const float*)d_in[fb + 1];
    const float* cosT = (const float*)d_in[fb + 2];
    const float* sinT = (const float*)d_in[fb + 3];
    const float* W[8]  = { (const float*)d_in[8],  (const float*)d_in[10],
                           (const float*)d_in[12], (const float*)d_in[14],
                           (const float*)d_in[16], (const float*)d_in[18],
                           (const float*)d_in[20], (const float*)d_in[22] };
    const float* biasIn[8] = { (const float*)d_in[9],  (const float*)d_in[11],
                               (const float*)d_in[13], (const float*)d_in[15],
                               (const float*)d_in[17], (const float*)d_in[19],
                               (const float*)d_in[21], (const float*)d_in[23] };
    const float* gq     = (const float*)d_in[24];
    const float* gk     = (const float*)d_in[25];
    const float* gq_add = (const float*)d_in[26];
    const float* gk_add = (const float*)d_in[27];

    float* out = (float*)d_out;

    __nv_bfloat16 *Whi, *Wlo, *Hhi, *Hlo, *Ehi, *Elo, *Shi, *Slo;
    __nv_bfloat16 *Qhp, *Qlp, *Khp, *Klp, *Vhp, *Vlp;
    cudaGetSymbolAddress((void**)&Whi, g_Whi);
    cudaGetSymbolAddress((void**)&Wlo, g_Wlo);
    cudaGetSymbolAddress((void**)&Hhi, g_Hhi);
    cudaGetSymbolAddress((void**)&Hlo, g_Hlo);
    cudaGetSymbolAddress((void**)&Ehi, g_Ehi);
    cudaGetSymbolAddress((void**)&Elo, g_Elo);
    cudaGetSymbolAddress((void**)&Shi, g_Shi);
    cudaGetSymbolAddress((void**)&Slo, g_Slo);
    cudaGetSymbolAddress((void**)&Qhp, g_Qh);
    cudaGetSymbolAddress((void**)&Qlp, g_Ql);
    cudaGetSymbolAddress((void**)&Khp, g_Kh);
    cudaGetSymbolAddress((void**)&Klp, g_Kl);
    cudaGetSymbolAddress((void**)&Vhp, g_Vh);
    cudaGetSymbolAddress((void**)&Vlp, g_Vl);

    cudaFuncSetAttribute(qkv_mma, cudaFuncAttributeMaxDynamicSharedMemorySize, GEMM_SMEM);
    cudaFuncSetAttribute(wo_mma, cudaFuncAttributeMaxDynamicSharedMemorySize, GEMM_SMEM);
    cudaFuncSetAttribute(attn_mma, cudaFuncAttributeMaxDynamicSharedMemorySize, ATT_SMEM2);

    // 1) merged weight transpose+split
    WSplitArgs ws;
    for (int i = 0; i < 8; i++) ws.W[i] = W[i];
    ws.Whi = Whi; ws.Wlo = Wlo;
    wsplit_all<<<dim3(DD / 32, DD / 32, 8), dim3(32, 8)>>>(ws);

    // 2) activation splits
    asplit_kernel<<<(M_IMG * DD / 4 + 255) / 256, 256>>>(hidden, Hhi, Hlo, M_IMG * DD / 4);
    asplit_kernel<<<(M_TXT * DD / 4 + 255) / 256, 256>>>(enc, Ehi, Elo, M_TXT * DD / 4);

    // 3) unified QKV projection + fused norm/rope/split
    const size_t WN = (size_t)DD * DD;
    QKVArgs qa;
    qa.Hhi = Hhi; qa.Hlo = Hlo; qa.Ehi = Ehi; qa.Elo = Elo;
    for (int i = 0; i < 6; i++) {
        qa.Wh[i] = Whi + (size_t)i * WN;
        qa.Wl[i] = Wlo + (size_t)i * WN;
        qa.bias[i] = biasIn[i];
    }
    qa.gq = gq; qa.gk = gk; qa.gqa = gq_add; qa.gka = gk_add;
    qa.cosI = cosI; qa.sinI = sinI; qa.cosT = cosT; qa.sinT = sinT;
    qa.Qh = Qhp; qa.Ql = Qlp; qa.Kh = Khp; qa.Kl = Klp; qa.Vh = Vhp; qa.Vl = Vlp;
    qkv_mma<<<dim3(DD / 128, 36, 3), 256, GEMM_SMEM>>>(qa);

    // 4) HMMA attention, BQ=64/BK=32, 2 CTAs/SM
    attn_mma<<<dim3(S_TOT / 64, BB * NH), 128, ATT_SMEM2>>>(
        Qhp, Qlp, Khp, Klp, Vhp, Vlp, mask, Shi, Slo);

    // 5) unified output projections
    WOArgs wa;
    wa.Shi = Shi; wa.Slo = Slo;
    wa.WhImg = Whi + 6 * WN; wa.WlImg = Wlo + 6 * WN;
    wa.WhTxt = Whi + 7 * WN; wa.WlTxt = Wlo + 7 * WN;
    wa.bImg = biasIn[6]; wa.bTxt = biasIn[7];
    wa.outImg = out; wa.outTxt = out + IMG_OUT_ELEMS;
    wo_mma<<<dim3(DD / 128, 36), 256, GEMM_SMEM>>>(wa);
}

// round 17
// speedup vs baseline: 1.0154x; 1.0154x over previous
#include <cuda_runtime.h>
#include <cuda_bf16.h>
#include <math.h>
#include <stdint.h>

// ---------------- problem constants ----------------
#define BB     2
#define S_IMG  2048
#define S_TXT  256
#define S_TOT  2304
#define NH     24
#define DHD    128
#define DD     3072
#define ATT_SCALE 0.08838834764831845f
#define RMS_EPS   1e-5f

#define M_IMG  (BB * S_IMG)          // 4096
#define M_TXT  (BB * S_TXT)          // 512
#define M_O    (BB * S_TOT)          // 4608
#define IMG_OUT_ELEMS (M_IMG * DD)

// ---------------- device scratch ----------------
__device__ __nv_bfloat16 g_Qh[BB * NH * S_TOT * DHD], g_Ql[BB * NH * S_TOT * DHD];
__device__ __nv_bfloat16 g_Kh[BB * NH * S_TOT * DHD], g_Kl[BB * NH * S_TOT * DHD];
__device__ __nv_bfloat16 g_Vh[BB * NH * S_TOT * DHD], g_Vl[BB * NH * S_TOT * DHD];

__device__ __nv_bfloat16 g_Whi[8][DD * DD];   // transposed [N,K] bf16 hi
__device__ __nv_bfloat16 g_Wlo[8][DD * DD];   // transposed [N,K] bf16 lo
__device__ __nv_bfloat16 g_Hhi[M_IMG * DD], g_Hlo[M_IMG * DD];
__device__ __nv_bfloat16 g_Ehi[M_TXT * DD], g_Elo[M_TXT * DD];
__device__ __nv_bfloat16 g_Shi[M_O * DD],  g_Slo[M_O * DD];   // attn-out split [B,S,D]

// ---------------- PTX helpers ----------------
__device__ __forceinline__ uint32_t smem_u32(const void* p) {
    uint32_t a;
    asm("{ .reg .u64 t; cvta.to.shared.u64 t, %1; cvt.u32.u64 %0, t; }" : "=r"(a) : "l"(p));
    return a;
}
#define CP_ASYNC16(sa, gp) \
    asm volatile("cp.async.cg.shared.global [%0], [%1], 16;" :: "r"(sa), "l"(gp) : "memory")
#define CP_COMMIT() asm volatile("cp.async.commit_group;" ::: "memory")
#define CP_WAIT(n)  asm volatile("cp.async.wait_group %0;" :: "n"(n) : "memory")

__device__ __forceinline__ void ldsm_x4(uint32_t& r0, uint32_t& r1, uint32_t& r2,
                                        uint32_t& r3, uint32_t addr) {
    asm volatile("ldmatrix.sync.aligned.m8n8.x4.shared.b16 {%0,%1,%2,%3}, [%4];"
                 : "=r"(r0), "=r"(r1), "=r"(r2), "=r"(r3) : "r"(addr));
}
__device__ __forceinline__ void ldsm_x4_t(uint32_t& r0, uint32_t& r1, uint32_t& r2,
                                          uint32_t& r3, uint32_t addr) {
    asm volatile("ldmatrix.sync.aligned.m8n8.x4.trans.shared.b16 {%0,%1,%2,%3}, [%4];"
                 : "=r"(r0), "=r"(r1), "=r"(r2), "=r"(r3) : "r"(addr));
}
__device__ __forceinline__ void mma16816(float* c, const uint32_t* a, const uint32_t* b) {
    asm volatile(
        "mma.sync.aligned.m16n8k16.row.col.f32.bf16.bf16.f32 "
        "{%0,%1,%2,%3}, {%4,%5,%6,%7}, {%8,%9}, {%0,%1,%2,%3};"
        : "+f"(c[0]), "+f"(c[1]), "+f"(c[2]), "+f"(c[3])
        : "r"(a[0]), "r"(a[1]), "r"(a[2]), "r"(a[3]), "r"(b[0]), "r"(b[1]));
}
__device__ __forceinline__ uint32_t pack_bf2(float a, float b) {
    uint32_t r;
    asm("cvt.rn.bf16x2.f32 %0, %1, %2;" : "=r"(r) : "f"(b), "f"(a));
    return r;
}

// ---------------- gemm smem geometry (2-stage, 2 CTAs/SM) ----------------
#define KC     32
#define NIT    (DD / KC)          // 96
#define ROWB   80
#define TILEB  (128 * ROWB)       // 10240
#define STAGEB (4 * TILEB)        // 40960
#define GEMM_SMEM (2 * STAGEB)    // 81920

// ---------------- kernel arg structs ----------------
struct QKVArgs {
    const __nv_bfloat16 *Hhi, *Hlo, *Ehi, *Elo;
    const __nv_bfloat16 *Wh[6], *Wl[6];
    const float *bias[6];
    const float *gq, *gk, *gqa, *gka;
    const float *cosI, *sinI, *cosT, *sinT;
    __nv_bfloat16 *Qh, *Ql, *Kh, *Kl, *Vh, *Vl;
};
struct WOArgs {
    const __nv_bfloat16 *Shi, *Slo;
    const __nv_bfloat16 *WhImg, *WlImg, *WhTxt, *WlTxt;
    const float *bImg, *bTxt;
    float *outImg, *outTxt;
};
struct WSplitArgs {
    const float* W[8];
    __nv_bfloat16 *Whi, *Wlo;
};

// =============================================================================
// Unified QKV projection, 2-stage cp.async, 2 CTAs/SM.
// MMA passes separated (hi*hi x16, hi*lo x16, lo*hi x16) for dependency distance.
// =============================================================================
__global__ void __launch_bounds__(256, 2) qkv_mma(QKVArgs P)
{
    extern __shared__ char smraw[];
    const uint32_t sb = smem_u32(smraw);
    const int t = threadIdx.x, lane = t & 31, wid = t >> 5;
    const int warp_m = wid & 1, warp_n = wid >> 1;
    const int z = blockIdx.z;
    const bool img = (blockIdx.y < 32);
    const int bm = (img ? blockIdx.y : (blockIdx.y - 32)) << 7;
    const int bn = blockIdx.x << 7;
    const int wi = img ? z : (z + 3);

    const __nv_bfloat16* Ahi = img ? P.Hhi : P.Ehi;
    const __nv_bfloat16* Alo = img ? P.Hlo : P.Elo;
    const __nv_bfloat16* Bhi = P.Wh[wi];
    const __nv_bfloat16* Blo = P.Wl[wi];
    const float* bias = P.bias[wi];

    const __nv_bfloat16* gsrc[8];
    uint32_t sdst[8];
#pragma unroll
    for (int i = 0; i < 8; i++) {
        int buf = i >> 1;
        int c = t + 256 * (i & 1);
        int row = c >> 2, kc = c & 3;
        const __nv_bfloat16* base = (buf == 0) ? Ahi : (buf == 1) ? Alo
                                  : (buf == 2) ? Bhi : Blo;
        long grow = (buf < 2) ? (long)(bm + row) : (long)(bn + row);
        gsrc[i] = base + (size_t)grow * DD + kc * 8;
        sdst[i] = sb + buf * TILEB + row * ROWB + kc * 16;
    }

    const uint32_t aBase = sb + (warp_m * 64 + (lane & 15)) * ROWB + (lane >> 4) * 16;
    const int brow = (lane & 7) + (((lane >> 4) & 1) << 3);
    const int bkh  = (lane >> 3) & 1;
    const uint32_t bBase = sb + 2 * TILEB + (warp_n * 32 + brow) * ROWB + bkh * 16;

    float acc[4][4][4];
#pragma unroll
    for (int mf = 0; mf < 4; mf++)
#pragma unroll
        for (int nf = 0; nf < 4; nf++)
#pragma unroll
            for (int r = 0; r < 4; r++) acc[mf][nf][r] = 0.f;

    {
#pragma unroll
        for (int i = 0; i < 8; i++) CP_ASYNC16(sdst[i], gsrc[i]);
        CP_COMMIT();
    }

    for (int it = 0; it < NIT; it++) {
        const int s = it & 1;
        if (it + 1 < NIT) {
            const int k0 = (it + 1) * KC;
            const uint32_t so = (s ^ 1) * STAGEB;
#pragma unroll
            for (int i = 0; i < 8; i++) CP_ASYNC16(sdst[i] + so, gsrc[i] + k0);
            CP_COMMIT();
            CP_WAIT(1);
        } else {
            CP_WAIT(0);
        }
        __syncthreads();

        const uint32_t sbase = s * STAGEB;
#pragma unroll
        for (int ks = 0; ks < 2; ks++) {
            uint32_t ah[4][4], al[4][4];
#pragma unroll
            for (int mf = 0; mf < 4; mf++) {
                uint32_t ad = aBase + sbase + mf * (16 * ROWB) + ks * 32;
                ldsm_x4(ah[mf][0], ah[mf][1], ah[mf][2], ah[mf][3], ad);
                ldsm_x4(al[mf][0], al[mf][1], al[mf][2], al[mf][3], ad + TILEB);
            }
            uint32_t bh[4][2], bl2[4][2];
#pragma unroll
            for (int nf2 = 0; nf2 < 2; nf2++) {
                uint32_t bd = bBase + sbase + nf2 * (16 * ROWB) + ks * 32;
                ldsm_x4(bh[2*nf2][0], bh[2*nf2][1], bh[2*nf2+1][0], bh[2*nf2+1][1], bd);
                ldsm_x4(bl2[2*nf2][0], bl2[2*nf2][1], bl2[2*nf2+1][0], bl2[2*nf2+1][1], bd + TILEB);
            }
            // three separated passes: per-acc order hi*hi, hi*lo, lo*hi preserved
#pragma unroll
            for (int mf = 0; mf < 4; mf++)
#pragma unroll
                for (int nf = 0; nf < 4; nf++)
                    mma16816(acc[mf][nf], ah[mf], bh[nf]);
#pragma unroll
            for (int mf = 0; mf < 4; mf++)
#pragma unroll
                for (int nf = 0; nf < 4; nf++)
                    mma16816(acc[mf][nf], ah[mf], bl2[nf]);
#pragma unroll
            for (int mf = 0; mf < 4; mf++)
#pragma unroll
                for (int nf = 0; nf < 4; nf++)
                    mma16816(acc[mf][nf], al[mf], bh[nf]);
        }
        __syncthreads();
    }

    // ---------------- epilogue ----------------
    const int rgrp = lane >> 2, qlane = lane & 3;
    const int h = blockIdx.x;
    const int seg = img ? S_IMG : S_TXT;
    const int sofs = img ? 0 : S_IMG;
    __nv_bfloat16* Xh = (z == 0) ? P.Qh : (z == 1) ? P.Kh : P.Vh;
    __nv_bfloat16* Xl = (z == 0) ? P.Ql : (z == 1) ? P.Kl : P.Vl;

#pragma unroll
    for (int mf = 0; mf < 4; mf++)
#pragma unroll
        for (int nf = 0; nf < 4; nf++) {
            int colg = bn + warp_n * 32 + nf * 8 + qlane * 2;
            float2 bv = *(const float2*)(bias + colg);
            acc[mf][nf][0] += bv.x; acc[mf][nf][1] += bv.y;
            acc[mf][nf][2] += bv.x; acc[mf][nf][3] += bv.y;
        }

    float rns[4][2];
    if (z < 2) {
        float* ssum = (float*)smraw;
#pragma unroll
        for (int mf = 0; mf < 4; mf++)
#pragma unroll
            for (int half = 0; half < 2; half++) {
                float ss = 0.f;
#pragma unroll
                for (int nf = 0; nf < 4; nf++) {
                    float x0 = acc[mf][nf][half * 2 + 0];
                    float x1 = acc[mf][nf][half * 2 + 1];
                    ss += x0 * x0 + x1 * x1;
                }
                ss += __shfl_xor_sync(0xffffffffu, ss, 1);
                ss += __shfl_xor_sync(0xffffffffu, ss, 2);
                if (qlane == 0)
                    ssum[(warp_m * 64 + mf * 16 + half * 8 + rgrp) * 4 + warp_n] = ss;
            }
        __syncthreads();
#pragma unroll
        for (int mf = 0; mf < 4; mf++)
#pragma unroll
            for (int half = 0; half < 2; half++) {
                int lrow = warp_m * 64 + mf * 16 + half * 8 + rgrp;
                float tot = ssum[lrow * 4 + 0] + ssum[lrow * 4 + 1] +
                            ssum[lrow * 4 + 2] + ssum[lrow * 4 + 3];
                rns[mf][half] = rsqrtf(tot * (1.f / DHD) + RMS_EPS);
            }
    }

    const float* g = (z == 0) ? (img ? P.gq : P.gqa)
                   : (z == 1) ? (img ? P.gk : P.gka) : (const float*)0;
    const float* cosT2 = img ? P.cosI : P.cosT;
    const float* sinT2 = img ? P.sinI : P.sinT;

#pragma unroll
    for (int mf = 0; mf < 4; mf++)
#pragma unroll
        for (int half = 0; half < 2; half++) {
            int lrow = warp_m * 64 + mf * 16 + half * 8 + rgrp;
            int m = bm + lrow;
            int b = m / seg, sl = m % seg;
            int sq = sofs + sl;
            size_t obase = (((size_t)(b * NH + h)) * S_TOT + sq) * DHD;
#pragma unroll
            for (int nf = 0; nf < 4; nf++) {
                int colh = warp_n * 32 + nf * 8 + qlane * 2;
                float x0 = acc[mf][nf][half * 2 + 0];
                float x1 = acc[mf][nf][half * 2 + 1];
                if (z < 2) {
                    float rn = rns[mf][half];
                    x0 *= rn * g[colh];
                    x1 *= rn * g[colh + 1];
                    int fi = colh >> 1;
                    float c = cosT2[sl * (DHD / 2) + fi];
                    float sv = sinT2[sl * (DHD / 2) + fi];
                    float o0 = x0 * c - x1 * sv;
                    float o1 = x0 * sv + x1 * c;
                    x0 = o0; x1 = o1;
                    if (z == 0) { x0 *= ATT_SCALE; x1 *= ATT_SCALE; }  // fold score scale into Q
                }
                uint32_t hp = pack_bf2(x0, x1);
                *(uint32_t*)((char*)Xh + (obase + colh) * 2) = hp;
                float ha = __uint_as_float((hp & 0xffffu) << 16);
                float hb = __uint_as_float(hp & 0xffff0000u);
                *(uint32_t*)((char*)Xl + (obase + colh) * 2) = pack_bf2(x0 - ha, x1 - hb);
            }
        }
}

// =============================================================================
// Unified output projection, same 3-pass MMA separation.
// =============================================================================
__global__ void __launch_bounds__(256, 2) wo_mma(WOArgs P)
{
    extern __shared__ char smraw[];
    const uint32_t sb = smem_u32(smraw);
    const int t = threadIdx.x, lane = t & 31, wid = t >> 5;
    const int warp_m = wid & 1, warp_n = wid >> 1;
    const bool img = (blockIdx.y < 32);
    const int bm = (img ? blockIdx.y : (blockIdx.y - 32)) << 7;
    const int bn = blockIdx.x << 7;

    const __nv_bfloat16* Bhi = img ? P.WhImg : P.WhTxt;
    const __nv_bfloat16* Blo = img ? P.WlImg : P.WlTxt;
    const float* bias = img ? P.bImg : P.bTxt;
    float* out = img ? P.outImg : P.outTxt;
    const int seg = img ? S_IMG : S_TXT;
    const int sofs = img ? 0 : S_IMG;

    const __nv_bfloat16* gsrc[8];
    uint32_t sdst[8];
#pragma unroll
    for (int i = 0; i < 8; i++) {
        int buf = i >> 1;
        int c = t + 256 * (i & 1);
        int row = c >> 2, kc = c & 3;
        const __nv_bfloat16* base = (buf == 0) ? P.Shi : (buf == 1) ? P.Slo
                                  : (buf == 2) ? Bhi : Blo;
        long grow;
        if (buf < 2) {
            int m = bm + row;
            grow = (long)(m / seg) * S_TOT + sofs + (m % seg);
        } else {
            grow = bn + row;
        }
        gsrc[i] = base + (size_t)grow * DD + kc * 8;
        sdst[i] = sb + buf * TILEB + row * ROWB + kc * 16;
    }

    const uint32_t aBase = sb + (warp_m * 64 + (lane & 15)) * ROWB + (lane >> 4) * 16;
    const int brow = (lane & 7) + (((lane >> 4) & 1) << 3);
    const int bkh  = (lane >> 3) & 1;
    const uint32_t bBase = sb + 2 * TILEB + (warp_n * 32 + brow) * ROWB + bkh * 16;

    float acc[4][4][4];
#pragma unroll
    for (int mf = 0; mf < 4; mf++)
#pragma unroll
        for (int nf = 0; nf < 4; nf++)
#pragma unroll
            for (int r = 0; r < 4; r++) acc[mf][nf][r] = 0.f;

    {
#pragma unroll
        for (int i = 0; i < 8; i++) CP_ASYNC16(sdst[i], gsrc[i]);
        CP_COMMIT();
    }

    for (int it = 0; it < NIT; it++) {
        const int s = it & 1;
        if (it + 1 < NIT) {
            const int k0 = (it + 1) * KC;
            const uint32_t so = (s ^ 1) * STAGEB;
#pragma unroll
            for (int i = 0; i < 8; i++) CP_ASYNC16(sdst[i] + so, gsrc[i] + k0);
            CP_COMMIT();
            CP_WAIT(1);
        } else {
            CP_WAIT(0);
        }
        __syncthreads();

        const uint32_t sbase = s * STAGEB;
#pragma unroll
        for (int ks = 0; ks < 2; ks++) {
            uint32_t ah[4][4], al[4][4];
#pragma unroll
            for (int mf = 0; mf < 4; mf++) {
                uint32_t ad = aBase + sbase + mf * (16 * ROWB) + ks * 32;
                ldsm_x4(ah[mf][0], ah[mf][1], ah[mf][2], ah[mf][3], ad);
                ldsm_x4(al[mf][0], al[mf][1], al[mf][2], al[mf][3], ad + TILEB);
            }
            uint32_t bh[4][2], bl2[4][2];
#pragma unroll
            for (int nf2 = 0; nf2 < 2; nf2++) {
                uint32_t bd = bBase + sbase + nf2 * (16 * ROWB) + ks * 32;
                ldsm_x4(bh[2*nf2][0], bh[2*nf2][1], bh[2*nf2+1][0], bh[2*nf2+1][1], bd);
                ldsm_x4(bl2[2*nf2][0], bl2[2*nf2][1], bl2[2*nf2+1][0], bl2[2*nf2+1][1], bd + TILEB);
            }
#pragma unroll
            for (int mf = 0; mf < 4; mf++)
#pragma unroll
                for (int nf = 0; nf < 4; nf++)
                    mma16816(acc[mf][nf], ah[mf], bh[nf]);
#pragma unroll
            for (int mf = 0; mf < 4; mf++)
#pragma unroll
                for (int nf = 0; nf < 4; nf++)
                    mma16816(acc[mf][nf], ah[mf], bl2[nf]);
#pragma unroll
            for (int mf = 0; mf < 4; mf++)
#pragma unroll
                for (int nf = 0; nf < 4; nf++)
                    mma16816(acc[mf][nf], al[mf], bh[nf]);
        }
        __syncthreads();
    }

#pragma unroll
    for (int mf = 0; mf < 4; mf++) {
        const int rbase = bm + warp_m * 64 + mf * 16 + (lane >> 2);
#pragma unroll
        for (int half = 0; half < 2; half++) {
            const int mrow = rbase + half * 8;
            float* orow = out + (size_t)mrow * DD;
#pragma unroll
            for (int nf = 0; nf < 4; nf++) {
                const int col = bn + warp_n * 32 + nf * 8 + (lane & 3) * 2;
                float2 bv = *(const float2*)(bias + col);
                float2 v;
                v.x = acc[mf][nf][half * 2 + 0] + bv.x;
                v.y = acc[mf][nf][half * 2 + 1] + bv.y;
                *(float2*)(orow + col) = v;
            }
        }
    }
}

// =============================================================================
// merged weight transpose + bf16 split: grid (96, 96, 8)
// =============================================================================
__global__ void __launch_bounds__(256) wsplit_all(WSplitArgs P)
{
    __shared__ float ts[32][33];
    const int tx = threadIdx.x, ty = threadIdx.y;
    const int n0 = blockIdx.x << 5, k0 = blockIdx.y << 5;
    const int z = blockIdx.z;
    const float* W = P.W[z];
    __nv_bfloat16* Thi = P.Whi + (size_t)z * DD * DD;
    __nv_bfloat16* Tlo = P.Wlo + (size_t)z * DD * DD;
#pragma unroll
    for (int i = 0; i < 4; i++)
        ts[ty + 8 * i][tx] = W[(size_t)(k0 + ty + 8 * i) * DD + n0 + tx];
    __syncthreads();
#pragma unroll
    for (int i = 0; i < 4; i++) {
        float v = ts[tx][ty + 8 * i];
        __nv_bfloat16 h = __float2bfloat16(v);
        float lo = v - __bfloat162float(h);
        size_t o = (size_t)(n0 + ty + 8 * i) * DD + k0 + tx;
        Thi[o] = h;
        Tlo[o] = __float2bfloat16(lo);
    }
}

// =============================================================================
// elementwise bf16 split
// =============================================================================
__global__ void __launch_bounds__(256) asplit_kernel(
    const float* __restrict__ X, __nv_bfloat16* __restrict__ hi,
    __nv_bfloat16* __restrict__ lo, int n4)
{
    int i = blockIdx.x * 256 + threadIdx.x;
    if (i >= n4) return;
    float4 v = ((const float4*)X)[i];
    __nv_bfloat16 h0 = __float2bfloat16(v.x), h1 = __float2bfloat16(v.y);
    __nv_bfloat16 h2 = __float2bfloat16(v.z), h3 = __float2bfloat16(v.w);
    __nv_bfloat162* hp = (__nv_bfloat162*)hi;
    __nv_bfloat162* lp = (__nv_bfloat162*)lo;
    hp[2 * i + 0] = __nv_bfloat162(h0, h1);
    hp[2 * i + 1] = __nv_bfloat162(h2, h3);
    lp[2 * i + 0] = __nv_bfloat162(__float2bfloat16(v.x - __bfloat162float(h0)),
                                   __float2bfloat16(v.y - __bfloat162float(h1)));
    lp[2 * i + 1] = __nv_bfloat162(__float2bfloat16(v.z - __bfloat162float(h2)),
                                   __float2bfloat16(v.w - __bfloat162float(h3)));
}

// =============================================================================
// HMMA flash attention (R12 geometry: BQ=128, BK=64, 8 warps, 1 CTA/SM),
// with pair-restructured MMA ordering in QK^T and PV.
// Q pre-scaled by ATT_SCALE in projection -> no per-iter score scaling.
// =============================================================================
#define SPB   272
#define ATSB  (64 * SPB)
#define AQB   (128 * SPB)
#define SM_QH 0
#define SM_QL AQB
#define SM_ST0 (2 * AQB)
#define SM_STSZ (4 * ATSB)
#define SM_BIAS (SM_ST0 + 2 * SM_STSZ)
#define ATT_SMEM (SM_BIAS + S_TXT * 4)
#define NKT (S_TOT / 64)

__global__ void __launch_bounds__(256, 1) attn_mma(
    const __nv_bfloat16* __restrict__ Qh, const __nv_bfloat16* __restrict__ Ql,
    const __nv_bfloat16* __restrict__ Kh, const __nv_bfloat16* __restrict__ Kl,
    const __nv_bfloat16* __restrict__ Vh, const __nv_bfloat16* __restrict__ Vl,
    const int* __restrict__ mask,
    __nv_bfloat16* __restrict__ Ohi, __nv_bfloat16* __restrict__ Olo)
{
    extern __shared__ char smraw[];
    const uint32_t sb = smem_u32(smraw);
    const int t = threadIdx.x, lane = t & 31, w = t >> 5;
    const int bh = blockIdx.y, b = bh / NH, h = bh % NH;
    const int q0 = blockIdx.x * 128;
    const size_t bhoff = (size_t)bh * S_TOT * DHD;

    if (t < S_TXT)
        *(float*)(smraw + SM_BIAS + t * 4) = (mask[b * S_TXT + t] == 0) ? -1e9f : 0.f;

    const __nv_bfloat16* kvsrc[4] = { Kh + bhoff, Kl + bhoff, Vh + bhoff, Vl + bhoff };
    auto issue = [&](int kt, int s) {
        const uint32_t stb = sb + SM_ST0 + s * SM_STSZ;
        const int k0 = kt * 64;
#pragma unroll
        for (int c = 0; c < 16; c++) {
            int buf = c >> 2;
            int idx = t + 256 * (c & 3);
            int row = idx >> 4, ch = idx & 15;
            const __nv_bfloat16* gp = kvsrc[buf] + (size_t)(k0 + row) * DHD + ch * 8;
            uint32_t sa = stb + buf * ATSB + row * SPB + ch * 16;
            CP_ASYNC16(sa, gp);
        }
    };

    issue(0, 0);
    CP_COMMIT();

    {
        const __nv_bfloat16* qsrc[2] = { Qh + bhoff + (size_t)q0 * DHD,
                                         Ql + bhoff + (size_t)q0 * DHD };
#pragma unroll
        for (int i = 0; i < 16; i++) {
            int idx = t + 256 * i;
            int buf = idx >> 11, rem = idx & 2047;
            int row = rem >> 4, ch = rem & 15;
            uint4 v = *(const uint4*)(qsrc[buf] + (size_t)row * DHD + ch * 8);
            *(uint4*)(smraw + buf * AQB + row * SPB + ch * 16) = v;
        }
    }

    const uint32_t qA = sb + SM_QH + (w * 16 + (lane & 15)) * SPB + (lane >> 4) * 16;
    const uint32_t kBrel = ((lane >> 4) * 8 + (lane & 7)) * SPB + ((lane >> 3) & 1) * 16;
    const uint32_t vBrel = (lane & 15) * SPB + (lane >> 4) * 16;

    float m0 = -1e30f, m1 = -1e30f, l0 = 0.f, l1 = 0.f;
    float o[16][4];
#pragma unroll
    for (int nf = 0; nf < 16; nf++)
#pragma unroll
        for (int e = 0; e < 4; e++) o[nf][e] = 0.f;

    for (int kt = 0; kt < NKT; kt++) {
        const int s = kt & 1;
        if (kt + 1 < NKT) { issue(kt + 1, s ^ 1); CP_COMMIT(); CP_WAIT(1); }
        else             { CP_WAIT(0); }
        __syncthreads();

        const uint32_t stb = sb + SM_ST0 + s * SM_STSZ;

        float sc[8][4];
#pragma unroll
        for (int j = 0; j < 8; j++)
#pragma unroll
            for (int e = 0; e < 4; e++) sc[j][e] = 0.f;

#pragma unroll
        for (int ks = 0; ks < 8; ks++) {
            uint32_t qh[4], ql[4];
            ldsm_x4(qh[0], qh[1], qh[2], qh[3], qA + ks * 32);
            ldsm_x4(ql[0], ql[1], ql[2], ql[3], qA + AQB + ks * 32);
            // process j2 in pairs: 4 independent acc chains, distance 4
#pragma unroll
            for (int jp = 0; jp < 2; jp++) {
                uint32_t kbA[4], klA[4], kbB[4], klB[4];
                uint32_t kdA = stb + kBrel + (2 * jp + 0) * (16 * SPB) + ks * 32;
                uint32_t kdB = stb + kBrel + (2 * jp + 1) * (16 * SPB) + ks * 32;
                ldsm_x4(kbA[0], kbA[1], kbA[2], kbA[3], kdA);
                ldsm_x4(klA[0], klA[1], klA[2], klA[3], kdA + ATSB);
                ldsm_x4(kbB[0], kbB[1], kbB[2], kbB[3], kdB);
                ldsm_x4(klB[0], klB[1], klB[2], klB[3], kdB + ATSB);
                float* s0 = sc[4 * jp + 0]; float* s1 = sc[4 * jp + 1];
                float* s2 = sc[4 * jp + 2]; float* s3 = sc[4 * jp + 3];
                mma16816(s0, qh, kbA); mma16816(s1, qh, kbA + 2);
                mma16816(s2, qh, kbB); mma16816(s3, qh, kbB + 2);
                mma16816(s0, qh, klA); mma16816(s1, qh, klA + 2);
                mma16816(s2, qh, klB); mma16816(s3, qh, klB + 2);
                mma16816(s0, ql, kbA); mma16816(s1, ql, kbA + 2);
                mma16816(s2, ql, kbB); mma16816(s3, ql, kbB + 2);
            }
        }

        // ---- mask bias (scores already scaled via Q)
        const bool txt_tile = (kt * 64 + 63 >= S_IMG);
        if (txt_tile) {
#pragma unroll
            for (int j = 0; j < 8; j++) {
                int colb = kt * 64 + j * 8 + (lane & 3) * 2;
                float b0v = 0.f, b1v = 0.f;
                if (colb + 0 >= S_IMG) b0v = *(float*)(smraw + SM_BIAS + (colb + 0 - S_IMG) * 4);
                if (colb + 1 >= S_IMG) b1v = *(float*)(smraw + SM_BIAS + (colb + 1 - S_IMG) * 4);
                sc[j][0] += b0v; sc[j][1] += b1v;
                sc[j][2] += b0v; sc[j][3] += b1v;
            }
        }

        float mx0 = -1e30f, mx1 = -1e30f;
#pragma unroll
        for (int j = 0; j < 8; j++) {
            mx0 = fmaxf(mx0, fmaxf(sc[j][0], sc[j][1]));
            mx1 = fmaxf(mx1, fmaxf(sc[j][2], sc[j][3]));
        }
        mx0 = fmaxf(mx0, __shfl_xor_sync(0xffffffffu, mx0, 1));
        mx0 = fmaxf(mx0, __shfl_xor_sync(0xffffffffu, mx0, 2));
        mx1 = fmaxf(mx1, __shfl_xor_sync(0xffffffffu, mx1, 1));
        mx1 = fmaxf(mx1, __shfl_xor_sync(0xffffffffu, mx1, 2));
        float mn0 = fmaxf(m0, mx0), mn1 = fmaxf(m1, mx1);
        float al0 = __expf(m0 - mn0), al1 = __expf(m1 - mn1);
        float rs0 = 0.f, rs1 = 0.f;
#pragma unroll
        for (int j = 0; j < 8; j++) {
            sc[j][0] = __expf(sc[j][0] - mn0); rs0 += sc[j][0];
            sc[j][1] = __expf(sc[j][1] - mn0); rs0 += sc[j][1];
            sc[j][2] = __expf(sc[j][2] - mn1); rs1 += sc[j][2];
            sc[j][3] = __expf(sc[j][3] - mn1); rs1 += sc[j][3];
        }
        rs0 += __shfl_xor_sync(0xffffffffu, rs0, 1);
        rs0 += __shfl_xor_sync(0xffffffffu, rs0, 2);
        rs1 += __shfl_xor_sync(0xffffffffu, rs1, 1);
        rs1 += __shfl_xor_sync(0xffffffffu, rs1, 2);
        l0 = l0 * al0 + rs0; m0 = mn0;
        l1 = l1 * al1 + rs1; m1 = mn1;
#pragma unroll
        for (int nf = 0; nf < 16; nf++) {
            o[nf][0] *= al0; o[nf][1] *= al0;
            o[nf][2] *= al1; o[nf][3] *= al1;
        }

        const uint32_t vtb = stb + 2 * ATSB;
#pragma unroll
        for (int ksv = 0; ksv < 4; ksv++) {
            uint32_t ah[4], alr[4];
#pragma unroll
            for (int q = 0; q < 4; q++) {
                int j = 2 * ksv + (q >> 1);
                float pa = sc[j][(q & 1) * 2 + 0];
                float pb = sc[j][(q & 1) * 2 + 1];
                uint32_t hp = pack_bf2(pa, pb);
                ah[q] = hp;
                float ha = __uint_as_float((hp & 0xffffu) << 16);
                float hb2 = __uint_as_float(hp & 0xffff0000u);
                alr[q] = pack_bf2(pa - ha, pb - hb2);
            }
            // ch pairs: 4 independent acc chains, distance 4
#pragma unroll
            for (int cp = 0; cp < 4; cp++) {
                uint32_t vbA[4], vlA[4], vbB[4], vlB[4];
                uint32_t vdA = vtb + vBrel + ksv * (16 * SPB) + (2 * cp + 0) * 32;
                uint32_t vdB = vtb + vBrel + ksv * (16 * SPB) + (2 * cp + 1) * 32;
                ldsm_x4_t(vbA[0], vbA[1], vbA[2], vbA[3], vdA);
                ldsm_x4_t(vlA[0], vlA[1], vlA[2], vlA[3], vdA + ATSB);
                ldsm_x4_t(vbB[0], vbB[1], vbB[2], vbB[3], vdB);
                ldsm_x4_t(vlB[0], vlB[1], vlB[2], vlB[3], vdB + ATSB);
                float* o0 = o[4 * cp + 0]; float* o1 = o[4 * cp + 1];
                float* o2 = o[4 * cp + 2]; float* o3 = o[4 * cp + 3];
                mma16816(o0, ah, vbA); mma16816(o1, ah, vbA + 2);
                mma16816(o2, ah, vbB); mma16816(o3, ah, vbB + 2);
                mma16816(o0, ah, vlA); mma16816(o1, ah, vlA + 2);
                mma16816(o2, ah, vlB); mma16816(o3, ah, vlB + 2);
                mma16816(o0, alr, vbA); mma16816(o1, alr, vbA + 2);
                mma16816(o2, alr, vbB); mma16816(o3, alr, vbB + 2);
            }
        }
        __syncthreads();
    }

    float inv0 = 1.f / l0, inv1 = 1.f / l1;
    int r0 = q0 + w * 16 + (lane >> 2), r1 = r0 + 8;
    size_t base0 = ((size_t)(b * S_TOT + r0)) * DD + h * DHD;
    size_t base1 = ((size_t)(b * S_TOT + r1)) * DD + h * DHD;
#pragma unroll
    for (int nf = 0; nf < 16; nf++) {
        int d = nf * 8 + (lane & 3) * 2;
        float v0 = o[nf][0] * inv0, v1 = o[nf][1] * inv0;
        uint32_t hp = pack_bf2(v0, v1);
        *(uint32_t*)((char*)Ohi + (base0 + d) * 2) = hp;
        float ha = __uint_as_float((hp & 0xffffu) << 16);
        float hb2 = __uint_as_float(hp & 0xffff0000u);
        *(uint32_t*)((char*)Olo + (base0 + d) * 2) = pack_bf2(v0 - ha, v1 - hb2);

        float u0 = o[nf][2] * inv1, u1 = o[nf][3] * inv1;
        uint32_t hq = pack_bf2(u0, u1);
        *(uint32_t*)((char*)Ohi + (base1 + d) * 2) = hq;
        float hc = __uint_as_float((hq & 0xffffu) << 16);
        float hd = __uint_as_float(hq & 0xffff0000u);
        *(uint32_t*)((char*)Olo + (base1 + d) * 2) = pack_bf2(u0 - hc, u1 - hd);
    }
}

// =============================================================================
// Launch
// =============================================================================
extern "C" void kernel_launch(void* const* d_in, const int* in_sizes, int n_in,
                              void* d_out, int out_size)
{
    const float* hidden = (const float*)d_in[0];
    const float* enc    = (const float*)d_in[1];
    const int*   mask   = (const int*)d_in[2];
    const int fb = (in_sizes[3] == 2) ? 4 : 3;
    const float* cosI = (const float*)d_in[fb + 0];
    const float* sinI = (const float*)d_in[fb + 1];
    const float* cosT = (const float*)d_in[fb + 2];
    const float* sinT = (const float*)d_in[fb + 3];
    const float* W[8]  = { (const float*)d_in[8],  (const float*)d_in[10],
                           (const float*)d_in[12], (const float*)d_in[14],
                           (const float*)d_in[16], (const float*)d_in[18],
                           (const float*)d_in[20], (const float*)d_in[22] };
    const float* biasIn[8] = { (const float*)d_in[9],  (const float*)d_in[11],
                               (const float*)d_in[13], (const float*)d_in[15],
                               (const float*)d_in[17], (const float*)d_in[19],
                               (const float*)d_in[21], (const float*)d_in[23] };
    const float* gq     = (const float*)d_in[24];
    const float* gk     = (const float*)d_in[25];
    const float* gq_add = (const float*)d_in[26];
    const float* gk_add = (const float*)d_in[27];

    float* out = (float*)d_out;

    __nv_bfloat16 *Whi, *Wlo, *Hhi, *Hlo, *Ehi, *Elo, *Shi, *Slo;
    __nv_bfloat16 *Qhp, *Qlp, *Khp, *Klp, *Vhp, *Vlp;
    cudaGetSymbolAddress((void**)&Whi, g_Whi);
    cudaGetSymbolAddress((void**)&Wlo, g_Wlo);
    cudaGetSymbolAddress((void**)&Hhi, g_Hhi);
    cudaGetSymbolAddress((void**)&Hlo, g_Hlo);
    cudaGetSymbolAddress((void**)&Ehi, g_Ehi);
    cudaGetSymbolAddress((void**)&Elo, g_Elo);
    cudaGetSymbolAddress((void**)&Shi, g_Shi);
    cudaGetSymbolAddress((void**)&Slo, g_Slo);
    cudaGetSymbolAddress((void**)&Qhp, g_Qh);
    cudaGetSymbolAddress((void**)&Qlp, g_Ql);
    cudaGetSymbolAddress((void**)&Khp, g_Kh);
    cudaGetSymbolAddress((void**)&Klp, g_Kl);
    cudaGetSymbolAddress((void**)&Vhp, g_Vh);
    cudaGetSymbolAddress((void**)&Vlp, g_Vl);

    cudaFuncSetAttribute(qkv_mma, cudaFuncAttributeMaxDynamicSharedMemorySize, GEMM_SMEM);
    cudaFuncSetAttribute(wo_mma, cudaFuncAttributeMaxDynamicSharedMemorySize, GEMM_SMEM);
    cudaFuncSetAttribute(attn_mma, cudaFuncAttributeMaxDynamicSharedMemorySize, ATT_SMEM);

    // 1) merged weight transpose+split
    WSplitArgs ws;
    for (int i = 0; i < 8; i++) ws.W[i] = W[i];
    ws.Whi = Whi; ws.Wlo = Wlo;
    wsplit_all<<<dim3(DD / 32, DD / 32, 8), dim3(32, 8)>>>(ws);

    // 2) activation splits
    asplit_kernel<<<(M_IMG * DD / 4 + 255) / 256, 256>>>(hidden, Hhi, Hlo, M_IMG * DD / 4);
    asplit_kernel<<<(M_TXT * DD / 4 + 255) / 256, 256>>>(enc, Ehi, Elo, M_TXT * DD / 4);

    // 3) unified QKV projection + fused norm/rope/scale/split
    const size_t WN = (size_t)DD * DD;
    QKVArgs qa;
    qa.Hhi = Hhi; qa.Hlo = Hlo; qa.Ehi = Ehi; qa.Elo = Elo;
    for (int i = 0; i < 6; i++) {
        qa.Wh[i] = Whi + (size_t)i * WN;
        qa.Wl[i] = Wlo + (size_t)i * WN;
        qa.bias[i] = biasIn[i];
    }
    qa.gq = gq; qa.gk = gk; qa.gqa = gq_add; qa.gka = gk_add;
    qa.cosI = cosI; qa.sinI = sinI; qa.cosT = cosT; qa.sinT = sinT;
    qa.Qh = Qhp; qa.Ql = Qlp; qa.Kh = Khp; qa.Kl = Klp; qa.Vh = Vhp; qa.Vl = Vlp;
    qkv_mma<<<dim3(DD / 128, 36, 3), 256, GEMM_SMEM>>>(qa);

    // 4) HMMA attention (R12 geometry, restructured MMA order)
    attn_mma<<<dim3(S_TOT / 128, BB * NH), 256, ATT_SMEM>>>(
        Qhp, Qlp, Khp, Klp, Vhp, Vlp, mask, Shi, Slo);

    // 5) unified output projections
    WOArgs wa;
    wa.Shi = Shi; wa.Slo = Slo;
    wa.WhImg = Whi + 6 * WN; wa.WlImg = Wlo + 6 * WN;
    wa.WhTxt = Whi + 7 * WN; wa.WlTxt = Wlo + 7 * WN;
    wa.bImg = biasIn[6]; wa.bTxt = biasIn[7];
    wa.outImg = out; wa.outTxt = out + IMG_OUT_ELEMS;
    wo_mma<<<dim3(DD / 128, 36), 256, GEMM_SMEM>>>(wa);
}